// round 3
// baseline (speedup 1.0000x reference)
#include <cuda_runtime.h>

#define B_   32
#define C_   3072
#define K_   11
#define HW_  784
#define NC_  200

// d_out layout: [afm (B,C,K)][scores (B,NC)][maps (B,K,HW)][attn (B,K)]
#define OFF_SCORES 1081344
#define OFF_MAPS   1087744
#define OFF_ATTN   1363712

__device__ float g_asq[16];
__device__ float g_f[B_ * C_];
__device__ int   g_ticket;

typedef unsigned long long u64;

__device__ __forceinline__ u64 pk(float a, float b) {
    u64 r; asm("mov.b64 %0,{%1,%2};" : "=l"(r) : "f"(a), "f"(b)); return r;
}
__device__ __forceinline__ float2 upk(u64 a) {
    float2 f; asm("mov.b64 {%0,%1},%2;" : "=f"(f.x), "=f"(f.y) : "l"(a)); return f;
}
__device__ __forceinline__ void fma2(u64& d, u64 a, u64 b) {
    asm("fma.rn.f32x2 %0,%1,%2,%0;" : "+l"(d) : "l"(a), "l"(b));
}
__device__ __forceinline__ u64 add2(u64 a, u64 b) {
    u64 r; asm("add.rn.f32x2 %0,%1,%2;" : "=l"(r) : "l"(a), "l"(b)); return r;
}

// ---------------------------------------------------------------------------
// a_sq[k] = sum_c w_land[k,c]^2  (block per k). Block 0 also resets the
// maps work-ticket (maps_kernel runs strictly after on the same stream).
// ---------------------------------------------------------------------------
__global__ void asq_kernel(const float* __restrict__ wl) {
    __shared__ float red[8];
    int k = blockIdx.x;
    if (k == 0 && threadIdx.x == 0) g_ticket = 0;
    const float* row = wl + k * C_;
    float s = 0.f;
    for (int c = threadIdx.x; c < C_; c += 256) { float v = row[c]; s = fmaf(v, v, s); }
    int warp = threadIdx.x >> 5, lane = threadIdx.x & 31;
    #pragma unroll
    for (int o = 16; o; o >>= 1) s += __shfl_xor_sync(0xffffffffu, s, o);
    if (lane == 0) red[warp] = s;
    __syncthreads();
    if (threadIdx.x == 0) {
        float t = 0.f;
        #pragma unroll
        for (int w = 0; w < 8; w++) t += red[w];
        g_asq[k] = t;
    }
}

// ---------------------------------------------------------------------------
// maps kernel v3: persistent 296 blocks, dynamic ticket over 392 units.
// Unit = 16 quads (64 pixels). Thread: 4 pixels x one of 16 channel segments.
// ---------------------------------------------------------------------------
#define MSEGS 16
#define MSEGC 192
#define MCH   48
#define MQPB  16
#define MUNITS 392
__global__ __launch_bounds__(256, 2) void maps_kernel(
    const float* __restrict__ x, const float* __restrict__ wl,
    float* __restrict__ maps)
{
    __shared__ __align__(16) float sraw[MSEGS * MCH * 12];   // 36864 B
    __shared__ int s_unit;
    int tid  = threadIdx.x;
    int q    = tid & 15;
    int seg  = tid >> 4;

    for (;;) {
        if (tid == 0) s_unit = atomicAdd(&g_ticket, 1);
        __syncthreads();
        int unit = s_unit;
        if (unit >= MUNITS) break;

        int gq  = unit * MQPB + q;
        int b   = gq / 196;
        int hw0 = (gq - b * 196) * 4;
        const float* xp = x + (size_t)b * (C_ * HW_) + (size_t)(seg * MSEGC) * HW_ + hw0;

        u64 accA[K_], accB[K_];
        #pragma unroll
        for (int k = 0; k < K_; k++) { accA[k] = 0ull; accB[k] = 0ull; }

        for (int ci = 0; ci < 4; ci++) {
            __syncthreads();
            for (int idx = tid; idx < MSEGS * MCH * K_; idx += 256) {   // 8448
                int k  = idx / (MSEGS * MCH);
                int r  = idx - k * (MSEGS * MCH);
                int s2 = r / MCH;
                int cc = r - s2 * MCH;
                sraw[(s2 * MCH + cc) * 12 + k] = wl[k * C_ + s2 * MSEGC + ci * MCH + cc];
            }
            __syncthreads();
            const float*  xc   = xp + (size_t)(ci * MCH) * HW_;
            const float4* wrow = (const float4*)(sraw + seg * MCH * 12);
            #pragma unroll 8
            for (int cc = 0; cc < MCH; cc++) {
                float4 xv = *(const float4*)(xc + (size_t)cc * HW_);
                float4 w0 = wrow[cc * 3 + 0];
                float4 w1 = wrow[cc * 3 + 1];
                float4 w2 = wrow[cc * 3 + 2];
                u64 xA = pk(xv.x, xv.y);
                u64 xB = pk(xv.z, xv.w);
                u64 wp;
                wp = pk(w0.x, w0.x); fma2(accA[0],  xA, wp); fma2(accB[0],  xB, wp);
                wp = pk(w0.y, w0.y); fma2(accA[1],  xA, wp); fma2(accB[1],  xB, wp);
                wp = pk(w0.z, w0.z); fma2(accA[2],  xA, wp); fma2(accB[2],  xB, wp);
                wp = pk(w0.w, w0.w); fma2(accA[3],  xA, wp); fma2(accB[3],  xB, wp);
                wp = pk(w1.x, w1.x); fma2(accA[4],  xA, wp); fma2(accB[4],  xB, wp);
                wp = pk(w1.y, w1.y); fma2(accA[5],  xA, wp); fma2(accB[5],  xB, wp);
                wp = pk(w1.z, w1.z); fma2(accA[6],  xA, wp); fma2(accB[6],  xB, wp);
                wp = pk(w1.w, w1.w); fma2(accA[7],  xA, wp); fma2(accB[7],  xB, wp);
                wp = pk(w2.x, w2.x); fma2(accA[8],  xA, wp); fma2(accB[8],  xB, wp);
                wp = pk(w2.y, w2.y); fma2(accA[9],  xA, wp); fma2(accB[9],  xB, wp);
                wp = pk(w2.z, w2.z); fma2(accA[10], xA, wp); fma2(accB[10], xB, wp);
            }
        }

        // fold lane pairs (seg even/odd within warp)
        #pragma unroll
        for (int k = 0; k < K_; k++) {
            accA[k] = add2(accA[k], __shfl_xor_sync(0xffffffffu, accA[k], 16));
            accB[k] = add2(accB[k], __shfl_xor_sync(0xffffffffu, accB[k], 16));
        }
        int warp = tid >> 5, lane = tid & 31;
        __syncthreads();
        float2* red = (float2*)sraw;   // [8 warps][16 quads][2 pairs][12 k]
        if (lane < 16) {
            int base = ((warp * 16 + lane) * 2) * 12;
            #pragma unroll
            for (int k = 0; k < K_; k++) {
                red[base + k]      = upk(accA[k]);
                red[base + 12 + k] = upk(accB[k]);
            }
        }
        __syncthreads();
        if (tid < 64) {
            int quad = tid >> 2, px = tid & 3;
            int pair = px >> 1, half = px & 1;
            float lg[K_];
            #pragma unroll
            for (int k = 0; k < K_; k++) {
                float s = 0.f;
                #pragma unroll
                for (int w = 0; w < 8; w++) {
                    float2 v = red[((w * 16 + quad) * 2 + pair) * 12 + k];
                    s += half ? v.y : v.x;
                }
                lg[k] = s;
            }
            float m = -1e30f;
            #pragma unroll
            for (int k = 0; k < K_; k++) {
                lg[k] = 2.f * lg[k] - g_asq[k];
                m = fmaxf(m, lg[k]);
            }
            float s = 0.f;
            #pragma unroll
            for (int k = 0; k < K_; k++) { lg[k] = __expf(lg[k] - m); s += lg[k]; }
            float inv = 1.f / s;
            int gq2 = unit * MQPB + quad;
            int b2  = gq2 / 196;
            int hw  = (gq2 - b2 * 196) * 4 + px;
            float* mp = maps + (size_t)b2 * (K_ * HW_) + hw;
            #pragma unroll
            for (int k = 0; k < K_; k++) mp[k * HW_] = lg[k] * inv;
        }
        __syncthreads();   // protect sraw/s_unit before next unit
    }
}

// ---------------------------------------------------------------------------
// feature kernel v3: 4 channels share each maps LDS.128.
// grid (48, B), 256 thr: 8 warps x 2 groups x 4 channels.
// ---------------------------------------------------------------------------
__global__ __launch_bounds__(256, 2) void feat_kernel(
    const float* __restrict__ x, const float* __restrict__ maps,
    const float* __restrict__ mod, float* __restrict__ afm,
    float* __restrict__ attn)
{
    __shared__ __align__(16) float sm[K_ * 800];   // 35200 B
    int b = blockIdx.y;
    const float* mp = maps + (size_t)b * (K_ * HW_);
    for (int idx = threadIdx.x; idx < K_ * HW_; idx += 256) {
        int k  = idx / HW_;
        int hw = idx - k * HW_;
        sm[k * 800 + hw] = mp[idx];
    }
    __syncthreads();
    int warp = threadIdx.x >> 5, lane = threadIdx.x & 31;

    if (blockIdx.x == 0) {   // attn folded in
        for (int k = warp; k < K_; k += 8) {
            float s = 0.f;
            for (int hw = lane; hw < HW_; hw += 32) s += sm[k * 800 + hw];
            #pragma unroll
            for (int o = 16; o; o >>= 1) s += __shfl_xor_sync(0xffffffffu, s, o);
            if (lane == 0) attn[b * K_ + k] = s;
        }
    }

    #pragma unroll 1
    for (int g = 0; g < 2; g++) {
        int c0 = blockIdx.x * 64 + warp * 8 + g * 4;
        const float* xp = x + ((size_t)b * C_ + c0) * HW_;
        u64 acc[4][K_];
        #pragma unroll
        for (int c = 0; c < 4; c++)
            #pragma unroll
            for (int k = 0; k < K_; k++) acc[c][k] = 0ull;
        #pragma unroll 1
        for (int i = 0; i < 7; i++) {
            int hw = i * 128 + lane * 4;
            if (hw < HW_) {
                ulonglong2 xv[4];
                #pragma unroll
                for (int c = 0; c < 4; c++)
                    xv[c] = *(const ulonglong2*)(xp + (size_t)c * HW_ + hw);
                #pragma unroll
                for (int k = 0; k < K_; k++) {
                    ulonglong2 mv = *(const ulonglong2*)(sm + k * 800 + hw);
                    #pragma unroll
                    for (int c = 0; c < 4; c++) {
                        fma2(acc[c][k], xv[c].x, mv.x);
                        fma2(acc[c][k], xv[c].y, mv.y);
                    }
                }
            }
        }
        const float inv = 1.f / (float)HW_;
        #pragma unroll 1
        for (int c = 0; c < 4; c++) {
            float sv[K_];
            #pragma unroll
            for (int k = 0; k < K_; k++) {
                float2 v = upk(acc[c][k]);
                sv[k] = v.x + v.y;
                #pragma unroll
                for (int o = 16; o; o >>= 1)
                    sv[k] += __shfl_xor_sync(0xffffffffu, sv[k], o);
            }
            if (lane == 0) {
                float f = 0.f;
                float* o0 = afm + ((size_t)b * C_ + c0 + c) * K_;
                #pragma unroll
                for (int k = 0; k < K_; k++) {
                    float v = sv[k] * inv * mod[(c0 + c) * K_ + k];
                    o0[k] = v;
                    f += v;
                }
                g_f[b * C_ + c0 + c] = f;
            }
        }
    }
}

// ---------------------------------------------------------------------------
// scores[b,n] = sum_c f[b,c] * w_cls[n,c]; warp handles 4 n interleaved.
// ---------------------------------------------------------------------------
__global__ __launch_bounds__(256) void score_kernel(
    const float* __restrict__ wcls, float* __restrict__ scores)
{
    __shared__ __align__(16) float sf[C_];
    int b = blockIdx.y;
    for (int idx = threadIdx.x; idx < C_; idx += 256) sf[idx] = g_f[b * C_ + idx];
    __syncthreads();
    int warp = threadIdx.x >> 5, lane = threadIdx.x & 31;
    int n0 = blockIdx.x * 32 + warp * 4;
    // clamp out-of-range rows to row 0 (results discarded at store)
    const float* wr[4];
    #pragma unroll
    for (int j = 0; j < 4; j++)
        wr[j] = wcls + (size_t)((n0 + j) < NC_ ? (n0 + j) : 0) * C_;
    float s0 = 0.f, s1 = 0.f, s2 = 0.f, s3 = 0.f;
    for (int c = lane * 4; c < C_; c += 128) {
        float4 fv = *(const float4*)(sf + c);
        float4 w0 = *(const float4*)(wr[0] + c);
        float4 w1 = *(const float4*)(wr[1] + c);
        float4 w2 = *(const float4*)(wr[2] + c);
        float4 w3 = *(const float4*)(wr[3] + c);
        s0 = fmaf(w0.x, fv.x, s0); s0 = fmaf(w0.y, fv.y, s0);
        s0 = fmaf(w0.z, fv.z, s0); s0 = fmaf(w0.w, fv.w, s0);
        s1 = fmaf(w1.x, fv.x, s1); s1 = fmaf(w1.y, fv.y, s1);
        s1 = fmaf(w1.z, fv.z, s1); s1 = fmaf(w1.w, fv.w, s1);
        s2 = fmaf(w2.x, fv.x, s2); s2 = fmaf(w2.y, fv.y, s2);
        s2 = fmaf(w2.z, fv.z, s2); s2 = fmaf(w2.w, fv.w, s2);
        s3 = fmaf(w3.x, fv.x, s3); s3 = fmaf(w3.y, fv.y, s3);
        s3 = fmaf(w3.z, fv.z, s3); s3 = fmaf(w3.w, fv.w, s3);
    }
    #pragma unroll
    for (int o = 16; o; o >>= 1) {
        s0 += __shfl_xor_sync(0xffffffffu, s0, o);
        s1 += __shfl_xor_sync(0xffffffffu, s1, o);
        s2 += __shfl_xor_sync(0xffffffffu, s2, o);
        s3 += __shfl_xor_sync(0xffffffffu, s3, o);
    }
    if (lane == 0) {
        if (n0 + 0 < NC_) scores[b * NC_ + n0 + 0] = s0;
        if (n0 + 1 < NC_) scores[b * NC_ + n0 + 1] = s1;
        if (n0 + 2 < NC_) scores[b * NC_ + n0 + 2] = s2;
        if (n0 + 3 < NC_) scores[b * NC_ + n0 + 3] = s3;
    }
}

// ---------------------------------------------------------------------------
extern "C" void kernel_launch(void* const* d_in, const int* in_sizes, int n_in,
                              void* d_out, int out_size) {
    const float* x    = (const float*)d_in[0];   // (B,C,H,W)
    const float* wl   = (const float*)d_in[1];   // (K,C)
    const float* mod  = (const float*)d_in[2];   // (1,C,K)
    const float* wcls = (const float*)d_in[3];   // (NC,C)
    float* out    = (float*)d_out;
    float* afm    = out;
    float* scores = out + OFF_SCORES;
    float* maps   = out + OFF_MAPS;
    float* attn   = out + OFF_ATTN;

    asq_kernel<<<K_, 256>>>(wl);
    maps_kernel<<<296, 256>>>(x, wl, maps);
    feat_kernel<<<dim3(48, B_), 256>>>(x, maps, mod, afm, attn);
    score_kernel<<<dim3(7, B_), 256>>>(wcls, scores);
}